// round 11
// baseline (speedup 1.0000x reference)
#include <cuda_runtime.h>
#include <cuda_bf16.h>

// Per-code coefficient table (constant memory). Every activation is:
//   t = v * (G*v^2 + A)            (A, G pre-scaled by log2(e))
//   E = 2^t,  R = 1/(1+E)
//   r = m*max(v, s*v) + p*R + d*(v*R) + e*min(E-1, 0) + q
#define LOG2E 1.4426950408889634f
__constant__ float4 COEF1[6] = {   // {s, A, G, m}
    {0.0f,  0.0f,           0.0f,           1.0f},  // relu
    {0.0f, -LOG2E,          0.0f,           0.0f},  // sigmoid
    {0.0f, -2.0f*LOG2E,     0.0f,           0.0f},  // tanh
    {0.0f,  LOG2E,          0.0f,           1.0f},  // elu
    {0.01f, 0.0f,           0.0f,           1.0f},  // leaky
    {0.0f, -2.3022082299f,  -0.1029432431f, 0.0f},  // gelu
};
__constant__ float4 COEF2[6] = {   // {p, q, d, e}
    {0.0f,  0.0f, 0.0f, 0.0f},   // relu
    {1.0f,  0.0f, 0.0f, 0.0f},   // sigmoid
    {2.0f, -1.0f, 0.0f, 0.0f},   // tanh
    {0.0f,  0.0f, 0.0f, 1.0f},   // elu
    {0.0f,  0.0f, 0.0f, 0.0f},   // leaky
    {0.0f,  0.0f, 1.0f, 0.0f},   // gelu
};

__device__ __forceinline__ float act_eval(float v, float4 c1, float4 c2) {
    float vv = v * v;
    float t  = v * fmaf(c1.z, vv, c1.y);            // cubic argument, log2-scaled
    float E;  asm("ex2.approx.ftz.f32 %0, %1;" : "=f"(E) : "f"(t));
    float den = 1.0f + E;
    float R;  asm("rcp.approx.ftz.f32 %0, %1;" : "=f"(R) : "f"(den));
    float mx = fmaxf(v, c1.x * v);                  // relu / leaky
    float mn = fminf(E - 1.0f, 0.0f);               // elu negative branch
    float r  = fmaf(c2.w, mn, c2.y);                // e*mn + q
    r = fmaf(c2.z, v * R, r);                       // + d*(v*R)
    r = fmaf(c2.x, R, r);                           // + p*R
    r = fmaf(c1.w, mx, r);                          // + m*mx
    return r;
}

// Software-pipelined row tiles: each thread covers TR*TILES rows of one
// float2 column pair. Tile t+1's loads are issued BEFORE tile t's compute,
// so LDGs stay outstanding through the compute+store phase (load duty cycle
// ~75% instead of ~0% during the tail). Tiles loop is unroll-1 so ptxas
// cannot re-batch all loads and blow the register budget (~40 regs target).
constexpr int TR    = 4;   // rows per tile
constexpr int TILES = 4;   // tiles per thread -> 16 rows/thread

__global__ __launch_bounds__(256) void act_pipe(
    const float2* __restrict__ x, const int2* __restrict__ codes,
    float2* __restrict__ out, int ncols2)
{
    int c = blockIdx.x * blockDim.x + threadIdx.x;
    if (c >= ncols2) return;

    const int2 cd = __ldg(&codes[c]);
    const float4 a1 = COEF1[cd.x], a2 = COEF2[cd.x];
    const float4 b1 = COEF1[cd.y], b2 = COEF2[cd.y];

    int base = blockIdx.y * (TR * TILES) * ncols2 + c;

    float2 cur[TR], nxt[TR];
    #pragma unroll
    for (int r = 0; r < TR; r++)
        cur[r] = x[base + r * ncols2];

    #pragma unroll 1
    for (int t = 0; t < TILES; t++) {
        int tb = base + t * TR * ncols2;

        if (t + 1 < TILES) {                       // prefetch next tile
            #pragma unroll
            for (int r = 0; r < TR; r++)
                nxt[r] = x[tb + (TR + r) * ncols2];
        }

        #pragma unroll
        for (int r = 0; r < TR; r++) {             // compute + store current
            float2 o;
            o.x = act_eval(cur[r].x, a1, a2);
            o.y = act_eval(cur[r].y, b1, b2);
            out[tb + r * ncols2] = o;
        }

        #pragma unroll
        for (int r = 0; r < TR; r++)               // rotate pipeline
            cur[r] = nxt[r];
    }
}

// Generic fallback (odd N, leftover rows).
__global__ __launch_bounds__(256) void act_scalar(
    const float* __restrict__ x, const int* __restrict__ codes,
    float* __restrict__ out, int N, int b_begin, int b_end)
{
    int c = blockIdx.x * blockDim.x + threadIdx.x;
    if (c >= N) return;
    int code = codes[c];
    const float4 c1 = COEF1[code], c2 = COEF2[code];
    for (int b = b_begin; b < b_end; b++) {
        long idx = (long)b * N + c;
        out[idx] = act_eval(x[idx], c1, c2);
    }
}

extern "C" void kernel_launch(void* const* d_in, const int* in_sizes, int n_in,
                              void* d_out, int out_size) {
    const float* x     = (const float*)d_in[0];
    const int*   codes = (const int*)d_in[1];
    float*       out   = (float*)d_out;

    int total = in_sizes[0];      // B * N
    int N     = in_sizes[1];      // C*H*W
    int B     = total / N;

    const int threads = 256;
    constexpr int RPT = TR * TILES;   // rows per thread

    if ((N & 1) == 0 && B >= RPT) {
        int ncols2 = N >> 1;
        int bx = (ncols2 + threads - 1) / threads;
        int by = B / RPT;
        dim3 grid(bx, by);
        act_pipe<<<grid, threads>>>(
            (const float2*)x, (const int2*)codes, (float2*)out, ncols2);
        int done = by * RPT;
        if (done < B) {
            int blocks = (N + threads - 1) / threads;
            act_scalar<<<blocks, threads>>>(x, codes, out, N, done, B);
        }
    } else {
        int blocks = (N + threads - 1) / threads;
        act_scalar<<<blocks, threads>>>(x, codes, out, N, 0, B);
    }
}